// round 1
// baseline (speedup 1.0000x reference)
#include <cuda_runtime.h>
#include <math.h>

#define BS 128
#define SL 512
#define HD 1024
#define DD 512
#define M_TOTAL (BS * SL)        // 65536
#define NEG_FILL -1000000.0f

#define TM 64
#define TN 64
#define TK 16
#define NT (DD / TN)             // 8 n-tiles

// Scratch: per-(row, n-tile) partial score contributions. 65536*8 floats = 2MB.
__device__ float g_partial[M_TOTAL * NT];

// ---------------------------------------------------------------------------
// Kernel 1: score partials.
//   acc[m,n] = sum_k x[m,k] * Wq[n,k]           (NT-layout GEMM, K=1024)
//   part[m, ntile] = sum_{n in tile} vq[n] * tanhf(acc[m,n] + bq[n])
// grid = (M_TOTAL/TM, DD/TN) = (1024, 8), block = 256 threads (16x16 * 4x4 regs)
// ---------------------------------------------------------------------------
__global__ __launch_bounds__(256)
void score_kernel(const float* __restrict__ x,
                  const float* __restrict__ Wq,
                  const float* __restrict__ bq,
                  const float* __restrict__ vq)
{
    __shared__ float As[TK][TM];   // [k][m] — transposed for vector LDS in hot loop
    __shared__ float Bs[TK][TN];   // [k][n]
    __shared__ float red[TM][16];  // epilogue reduction

    const int m0 = blockIdx.x * TM;
    const int n0 = blockIdx.y * TN;
    const int t  = threadIdx.x;        // 0..255
    const int tx = t & 15;             // n-quad index
    const int ty = t >> 4;             // m-quad index

    // loader mapping: each thread fetches one float4 of A and one of B per k-tile
    const int lr = t >> 2;             // row within tile: 0..63
    const int lc = (t & 3) << 2;       // col within k-tile: 0,4,8,12

    const float* xg = x  + (size_t)(m0 + lr) * HD + lc;
    const float* wg = Wq + (size_t)(n0 + lr) * HD + lc;

    float acc[4][4];
#pragma unroll
    for (int i = 0; i < 4; i++)
#pragma unroll
        for (int j = 0; j < 4; j++) acc[i][j] = 0.0f;

    for (int k0 = 0; k0 < HD; k0 += TK) {
        const float4 av = *reinterpret_cast<const float4*>(xg + k0);
        const float4 bv = *reinterpret_cast<const float4*>(wg + k0);

        __syncthreads();   // previous tile fully consumed
        As[lc + 0][lr] = av.x; As[lc + 1][lr] = av.y;
        As[lc + 2][lr] = av.z; As[lc + 3][lr] = av.w;
        Bs[lc + 0][lr] = bv.x; Bs[lc + 1][lr] = bv.y;
        Bs[lc + 2][lr] = bv.z; Bs[lc + 3][lr] = bv.w;
        __syncthreads();

#pragma unroll
        for (int kk = 0; kk < TK; kk++) {
            const float4 a = *reinterpret_cast<const float4*>(&As[kk][ty << 2]);
            const float4 b = *reinterpret_cast<const float4*>(&Bs[kk][tx << 2]);
            acc[0][0] += a.x * b.x; acc[0][1] += a.x * b.y;
            acc[0][2] += a.x * b.z; acc[0][3] += a.x * b.w;
            acc[1][0] += a.y * b.x; acc[1][1] += a.y * b.y;
            acc[1][2] += a.y * b.z; acc[1][3] += a.y * b.w;
            acc[2][0] += a.z * b.x; acc[2][1] += a.z * b.y;
            acc[2][2] += a.z * b.z; acc[2][3] += a.z * b.w;
            acc[3][0] += a.w * b.x; acc[3][1] += a.w * b.y;
            acc[3][2] += a.w * b.z; acc[3][3] += a.w * b.w;
        }
    }

    // Epilogue: tanh + vq dot, per m-row partial over this 64-col n-tile.
    const int nb = n0 + (tx << 2);
    const float bq0 = bq[nb + 0], bq1 = bq[nb + 1], bq2 = bq[nb + 2], bq3 = bq[nb + 3];
    const float vq0 = vq[nb + 0], vq1 = vq[nb + 1], vq2 = vq[nb + 2], vq3 = vq[nb + 3];

    float part[4];
#pragma unroll
    for (int i = 0; i < 4; i++) {
        part[i] = vq0 * tanhf(acc[i][0] + bq0)
                + vq1 * tanhf(acc[i][1] + bq1)
                + vq2 * tanhf(acc[i][2] + bq2)
                + vq3 * tanhf(acc[i][3] + bq3);
    }

#pragma unroll
    for (int i = 0; i < 4; i++) red[(ty << 2) + i][tx] = part[i];
    __syncthreads();

    if (t < TM) {
        float s = 0.0f;
#pragma unroll
        for (int j = 0; j < 16; j++) s += red[t][j];
        g_partial[(size_t)(m0 + t) * NT + blockIdx.y] = s;
    }
}

// ---------------------------------------------------------------------------
// Kernel 2: per-batch fused mask -> softmax -> weighted sum over sequence.
// grid = BS blocks, 256 threads. Each thread owns 4 h-columns (float4).
// ---------------------------------------------------------------------------
__global__ __launch_bounds__(256)
void out_kernel(const float* __restrict__ x,
                const int* __restrict__ mask,
                float* __restrict__ out)
{
    __shared__ float w[SL];
    __shared__ float rbuf[256];

    const int b = blockIdx.x;
    const int t = threadIdx.x;

    // 1) assemble scores from partials, apply mask
    for (int s = t; s < SL; s += 256) {
        const size_t m = (size_t)b * SL + s;
        float sc = 0.0f;
#pragma unroll
        for (int nt = 0; nt < NT; nt++) sc += g_partial[m * NT + nt];
        if (mask[m]) sc = NEG_FILL;
        w[s] = sc;
    }
    __syncthreads();

    // 2) block max
    float mx = -3.4e38f;
    for (int s = t; s < SL; s += 256) mx = fmaxf(mx, w[s]);
    rbuf[t] = mx;
    __syncthreads();
    for (int off = 128; off > 0; off >>= 1) {
        if (t < off) rbuf[t] = fmaxf(rbuf[t], rbuf[t + off]);
        __syncthreads();
    }
    const float gmax = rbuf[0];
    __syncthreads();

    // 3) exp + block sum
    float psum = 0.0f;
    for (int s = t; s < SL; s += 256) {
        const float e = __expf(w[s] - gmax);
        w[s] = e;
        psum += e;
    }
    rbuf[t] = psum;
    __syncthreads();
    for (int off = 128; off > 0; off >>= 1) {
        if (t < off) rbuf[t] += rbuf[t + off];
        __syncthreads();
    }
    const float inv = 1.0f / rbuf[0];
    __syncthreads();

    // 4) weighted sum over sequence: out[b, 4t..4t+3]
    const float* xb = x + (size_t)b * SL * HD + (t << 2);
    float4 acc = make_float4(0.f, 0.f, 0.f, 0.f);
#pragma unroll 4
    for (int s = 0; s < SL; s++) {
        const float ws = w[s];
        const float4 xv = *reinterpret_cast<const float4*>(xb + (size_t)s * HD);
        acc.x += ws * xv.x; acc.y += ws * xv.y;
        acc.z += ws * xv.z; acc.w += ws * xv.w;
    }
    acc.x *= inv; acc.y *= inv; acc.z *= inv; acc.w *= inv;
    *reinterpret_cast<float4*>(out + (size_t)b * HD + (t << 2)) = acc;
}

// ---------------------------------------------------------------------------
extern "C" void kernel_launch(void* const* d_in, const int* in_sizes, int n_in,
                              void* d_out, int out_size)
{
    const float* x    = (const float*)d_in[0];   // [128,512,1024] f32
    const int*   mask = (const int*)  d_in[1];   // [128,512] bool->int32
    const float* Wq   = (const float*)d_in[2];   // [512,1024] f32
    const float* bq   = (const float*)d_in[3];   // [512] f32
    const float* vq   = (const float*)d_in[4];   // [512] f32
    float* out = (float*)d_out;                  // [128,1024] f32

    dim3 g1(M_TOTAL / TM, DD / TN);              // (1024, 8)
    score_kernel<<<g1, 256>>>(x, Wq, bq, vq);
    out_kernel<<<BS, 256>>>(x, mask, out);
}

// round 3
// speedup vs baseline: 2.8425x; 2.8425x over previous
#include <cuda_runtime.h>
#include <cuda_fp16.h>
#include <math.h>
#include <stdint.h>

#define BS 128
#define SL 512
#define HD 1024
#define DD 512
#define M_TOTAL (BS * SL)          // 65536
#define KPHYS 2048                 // [x_hi | x_lo] physical K (halves)
#define KVIRT 3072                 // 3 split terms
#define NEG_FILL -1000000.0f

#define BM 128
#define BN 128
#define BK 64                      // halves per chunk
#define NCHUNK (KVIRT / BK)        // 48
#define STAGES 4
#define A_BYTES (BM * BK * 2)      // 16384
#define B_BYTES (BN * BK * 2)      // 16384
#define STAGE_BYTES (A_BYTES + B_BYTES)
#define SMEM_RED (128 * 2 * 4)     // sred[128][2] floats
#define SMEM_GEMM (STAGES * STAGE_BYTES + SMEM_RED)

// ---------------- device scratch (no allocations allowed) -------------------
__device__ __half g_A[(size_t)M_TOTAL * KPHYS];   // 268 MB
__device__ __half g_B[(size_t)DD * KPHYS];        // 2 MB
__device__ float  g_spart[M_TOTAL * 4];           // per-(row, n-block) partials
__device__ float  g_w[M_TOTAL];

// ---------------- helpers ----------------------------------------------------
__device__ __forceinline__ uint32_t smem_u32(const void* p) {
    uint32_t a;
    asm("{ .reg .u64 t; cvta.to.shared.u64 t, %1; cvt.u32.u64 %0, t; }" : "=r"(a) : "l"(p));
    return a;
}
#define CP16(dst, src) \
    asm volatile("cp.async.cg.shared.global [%0], [%1], 16;" :: "r"(dst), "l"(src) : "memory")
#define CP_COMMIT() asm volatile("cp.async.commit_group;" ::: "memory")
#define CP_WAIT2()  asm volatile("cp.async.wait_group 2;" ::: "memory")

__device__ __forceinline__ void ldsm_x4(uint32_t addr, uint32_t& r0, uint32_t& r1,
                                        uint32_t& r2, uint32_t& r3) {
    asm volatile("ldmatrix.sync.aligned.m8n8.x4.shared.b16 {%0,%1,%2,%3}, [%4];"
                 : "=r"(r0), "=r"(r1), "=r"(r2), "=r"(r3) : "r"(addr));
}
__device__ __forceinline__ void mma16816(float* c, const uint32_t* a,
                                         uint32_t b0, uint32_t b1) {
    asm volatile(
        "mma.sync.aligned.m16n8k16.row.col.f32.f16.f16.f32 "
        "{%0,%1,%2,%3},{%4,%5,%6,%7},{%8,%9},{%0,%1,%2,%3};"
        : "+f"(c[0]), "+f"(c[1]), "+f"(c[2]), "+f"(c[3])
        : "r"(a[0]), "r"(a[1]), "r"(a[2]), "r"(a[3]), "r"(b0), "r"(b1));
}

// ---------------------------------------------------------------------------
// Conversion: fp32 -> [hi | lo] fp16 split
// ---------------------------------------------------------------------------
__global__ __launch_bounds__(256) void conv_x_kernel(const float* __restrict__ x)
{
    size_t g = (size_t)blockIdx.x * 256 + threadIdx.x;
    size_t m = g >> 8;
    int kq = (int)(g & 255) << 2;
    float4 v = *reinterpret_cast<const float4*>(x + m * HD + kq);

    __half h0 = __float2half_rn(v.x), h1 = __float2half_rn(v.y);
    __half h2 = __float2half_rn(v.z), h3 = __float2half_rn(v.w);
    __half l0 = __float2half_rn(v.x - __half2float(h0));
    __half l1 = __float2half_rn(v.y - __half2float(h1));
    __half l2 = __float2half_rn(v.z - __half2float(h2));
    __half l3 = __float2half_rn(v.w - __half2float(h3));

    __half2* ph = reinterpret_cast<__half2*>(g_A + m * KPHYS + kq);
    __half2* pl = reinterpret_cast<__half2*>(g_A + m * KPHYS + 1024 + kq);
    ph[0] = __halves2half2(h0, h1); ph[1] = __halves2half2(h2, h3);
    pl[0] = __halves2half2(l0, l1); pl[1] = __halves2half2(l2, l3);
}

__global__ __launch_bounds__(256) void conv_w_kernel(const float* __restrict__ Wq)
{
    size_t g = (size_t)blockIdx.x * 256 + threadIdx.x;
    size_t n = g >> 8;
    int kq = (int)(g & 255) << 2;
    float4 v = *reinterpret_cast<const float4*>(Wq + n * HD + kq);

    __half h0 = __float2half_rn(v.x), h1 = __float2half_rn(v.y);
    __half h2 = __float2half_rn(v.z), h3 = __float2half_rn(v.w);
    __half l0 = __float2half_rn(v.x - __half2float(h0));
    __half l1 = __float2half_rn(v.y - __half2float(h1));
    __half l2 = __float2half_rn(v.z - __half2float(h2));
    __half l3 = __float2half_rn(v.w - __half2float(h3));

    __half2* ph = reinterpret_cast<__half2*>(g_B + n * KPHYS + kq);
    __half2* pl = reinterpret_cast<__half2*>(g_B + n * KPHYS + 1024 + kq);
    ph[0] = __halves2half2(h0, h1); ph[1] = __halves2half2(h2, h3);
    pl[0] = __halves2half2(l0, l1); pl[1] = __halves2half2(l2, l3);
}

// ---------------------------------------------------------------------------
// GEMM: D[128m x 128n] = sum over 3 split terms, + fused tanh/vq epilogue.
// grid = (512, 4). 256 threads = 8 warps as 4(m) x 2(n); warp tile 32x64.
// ---------------------------------------------------------------------------
__device__ __forceinline__ void load_chunk(int chunk, uint32_t stage, int m0, int n0,
                                           int tid)
{
    const int kv = chunk * BK;
    const int kA = (kv < 2048) ? kv : kv - 2048;   // [hi|lo|hi]
    const int kB = (kv < 1024) ? kv : kv - 1024;   // [hi|hi|lo]
    const __half* asrc = g_A + (size_t)m0 * KPHYS + kA;
    const __half* bsrc = g_B + (size_t)n0 * KPHYS + kB;

#pragma unroll
    for (int u = 0; u < 4; u++) {                  // A: 128 rows x 8 x 16B
        int idx = tid + u * 256;
        int r = idx >> 3, j = idx & 7;
        uint32_t dst = stage + r * 128 + ((j ^ (r & 7)) << 4);
        CP16(dst, asrc + (size_t)r * KPHYS + j * 8);
    }
#pragma unroll
    for (int u = 0; u < 4; u++) {                  // B: 128 rows x 8 x 16B
        int idx = tid + u * 256;
        int r = idx >> 3, j = idx & 7;
        uint32_t dst = stage + A_BYTES + r * 128 + ((j ^ (r & 7)) << 4);
        CP16(dst, bsrc + (size_t)r * KPHYS + j * 8);
    }
    CP_COMMIT();
}

__global__ __launch_bounds__(256, 1) void gemm_kernel(const float* __restrict__ bq,
                                                      const float* __restrict__ vq)
{
    extern __shared__ char smem[];
    const uint32_t sb = smem_u32(smem);
    const int tid = threadIdx.x;
    const int wid = tid >> 5, lane = tid & 31;
    const int wm = wid & 3, wn = wid >> 2;
    const int m0 = blockIdx.x * BM;
    const int nb = blockIdx.y;
    const int n0 = nb * BN;

    float acc[2][8][4];
#pragma unroll
    for (int i = 0; i < 2; i++)
#pragma unroll
        for (int j = 0; j < 8; j++)
#pragma unroll
            for (int k = 0; k < 4; k++) acc[i][j][k] = 0.0f;

    // ldmatrix per-thread row indices (fixed per thread)
    const int arow = wm * 32 + (lane & 15);                        // + mt*16
    const int aj   = (lane >> 4);                                  // + kk*2
    const int brow = wn * 64 + (lane & 7) + ((lane >> 4) & 1) * 8; // + nt2*16
    const int bj   = ((lane >> 3) & 1);                            // + kk*2

    load_chunk(0, sb + 0 * STAGE_BYTES, m0, n0, tid);
    load_chunk(1, sb + 1 * STAGE_BYTES, m0, n0, tid);
    load_chunk(2, sb + 2 * STAGE_BYTES, m0, n0, tid);

#pragma unroll 1
    for (int i = 0; i < NCHUNK; i++) {
        CP_WAIT2();                // oldest (chunk i) resident
        __syncthreads();

        const uint32_t sA = sb + (i & 3) * STAGE_BYTES;
        const uint32_t sB = sA + A_BYTES;

#pragma unroll
        for (int kk = 0; kk < 4; kk++) {
            uint32_t a0[4], a1[4];
            {
                int r = arow, j = kk * 2 + aj;
                ldsm_x4(sA + r * 128 + ((j ^ (r & 7)) << 4), a0[0], a0[1], a0[2], a0[3]);
                r = arow + 16;
                ldsm_x4(sA + r * 128 + ((j ^ (r & 7)) << 4), a1[0], a1[1], a1[2], a1[3]);
            }
#pragma unroll
            for (int nt2 = 0; nt2 < 4; nt2++) {
                uint32_t b0, b1, b2, b3;
                int r = brow + nt2 * 16, j = kk * 2 + bj;
                ldsm_x4(sB + r * 128 + ((j ^ (r & 7)) << 4), b0, b1, b2, b3);
                mma16816(acc[0][2 * nt2],     a0, b0, b1);
                mma16816(acc[0][2 * nt2 + 1], a0, b2, b3);
                mma16816(acc[1][2 * nt2],     a1, b0, b1);
                mma16816(acc[1][2 * nt2 + 1], a1, b2, b3);
            }
        }

        __syncthreads();           // everyone done with stage (i-1)%4 region reuse
        if (i + 3 < NCHUNK)
            load_chunk(i + 3, sb + ((i + 3) & 3) * STAGE_BYTES, m0, n0, tid);
    }

    // ---- epilogue: per-row sum of vq[n]*tanh(D+bq[n]) over this 128-n block ----
    float* sred = reinterpret_cast<float*>(smem + STAGES * STAGE_BYTES);
    const int g = lane >> 2, tig = lane & 3;

    float rs[2][2] = {{0.f, 0.f}, {0.f, 0.f}};
#pragma unroll
    for (int mt = 0; mt < 2; mt++) {
#pragma unroll
        for (int nt = 0; nt < 8; nt++) {
            const int n = n0 + wn * 64 + nt * 8 + 2 * tig;
            const float b0 = __ldg(bq + n), b1 = __ldg(bq + n + 1);
            const float v0 = __ldg(vq + n), v1 = __ldg(vq + n + 1);
            rs[mt][0] += v0 * tanhf(acc[mt][nt][0] + b0) + v1 * tanhf(acc[mt][nt][1] + b1);
            rs[mt][1] += v0 * tanhf(acc[mt][nt][2] + b0) + v1 * tanhf(acc[mt][nt][3] + b1);
        }
    }
#pragma unroll
    for (int d = 1; d <= 2; d <<= 1) {
#pragma unroll
        for (int mt = 0; mt < 2; mt++) {
            rs[mt][0] += __shfl_xor_sync(0xFFFFFFFF, rs[mt][0], d);
            rs[mt][1] += __shfl_xor_sync(0xFFFFFFFF, rs[mt][1], d);
        }
    }
    if (tig == 0) {
#pragma unroll
        for (int mt = 0; mt < 2; mt++) {
            sred[(wm * 32 + mt * 16 + g) * 2 + wn]     = rs[mt][0];
            sred[(wm * 32 + mt * 16 + g + 8) * 2 + wn] = rs[mt][1];
        }
    }
    __syncthreads();
    if (tid < 128)
        g_spart[(size_t)(m0 + tid) * 4 + nb] = sred[tid * 2] + sred[tid * 2 + 1];
}

// ---------------------------------------------------------------------------
// Softmax over sequence (per batch): combine 4 n-block partials, mask, softmax.
// ---------------------------------------------------------------------------
__global__ __launch_bounds__(256) void softmax_kernel(const int* __restrict__ mask)
{
    __shared__ float sc[SL];
    __shared__ float red[256];
    const int b = blockIdx.x, t = threadIdx.x;

    for (int s = t; s < SL; s += 256) {
        const size_t m = (size_t)b * SL + s;
        float v = g_spart[m * 4 + 0] + g_spart[m * 4 + 1]
                + g_spart[m * 4 + 2] + g_spart[m * 4 + 3];
        if (mask[m]) v = NEG_FILL;
        sc[s] = v;
    }
    __syncthreads();

    red[t] = fmaxf(sc[t], sc[t + 256]);
    __syncthreads();
    for (int off = 128; off > 0; off >>= 1) {
        if (t < off) red[t] = fmaxf(red[t], red[t + off]);
        __syncthreads();
    }
    const float gm = red[0];
    __syncthreads();

    const float e0 = __expf(sc[t] - gm);
    const float e1 = __expf(sc[t + 256] - gm);
    red[t] = e0 + e1;
    __syncthreads();
    for (int off = 128; off > 0; off >>= 1) {
        if (t < off) red[t] += red[t + off];
        __syncthreads();
    }
    const float inv = 1.0f / red[0];
    g_w[b * SL + t] = e0 * inv;
    g_w[b * SL + t + 256] = e1 * inv;
}

// ---------------------------------------------------------------------------
// Weighted sum: out[b, col] = sum_s w[b,s] * x[b,s,col].  grid (4, 128).
// ---------------------------------------------------------------------------
__global__ __launch_bounds__(256) void wsum_kernel(const float* __restrict__ x,
                                                   float* __restrict__ out)
{
    __shared__ float w[SL];
    const int b = blockIdx.y;
    const int col = blockIdx.x * 256 + threadIdx.x;

    w[threadIdx.x] = g_w[b * SL + threadIdx.x];
    w[threadIdx.x + 256] = g_w[b * SL + threadIdx.x + 256];
    __syncthreads();

    const float* xp = x + (size_t)b * SL * HD + col;
    float acc = 0.0f;
#pragma unroll 8
    for (int s = 0; s < SL; s++) acc += w[s] * xp[(size_t)s * HD];
    out[(size_t)b * HD + col] = acc;
}

// ---------------------------------------------------------------------------
extern "C" void kernel_launch(void* const* d_in, const int* in_sizes, int n_in,
                              void* d_out, int out_size)
{
    const float* x    = (const float*)d_in[0];   // [128,512,1024] f32
    const int*   mask = (const int*)  d_in[1];   // [128,512] int32
    const float* Wq   = (const float*)d_in[2];   // [512,1024] f32
    const float* bq   = (const float*)d_in[3];   // [512] f32
    const float* vq   = (const float*)d_in[4];   // [512] f32
    float* out = (float*)d_out;                  // [128,1024] f32

    cudaFuncSetAttribute(gemm_kernel, cudaFuncAttributeMaxDynamicSharedMemorySize, SMEM_GEMM);

    conv_x_kernel<<<(M_TOTAL * HD / 4) / 256, 256>>>(x);   // 65536 blocks
    conv_w_kernel<<<(DD * HD / 4) / 256, 256>>>(Wq);       // 512 blocks
    gemm_kernel<<<dim3(M_TOTAL / BM, DD / BN), 256, SMEM_GEMM>>>(bq, vq);
    softmax_kernel<<<BS, 256>>>(mask);
    wsum_kernel<<<dim3(4, BS), 256>>>(x, out);
}

// round 4
// speedup vs baseline: 4.3561x; 1.5325x over previous
#include <cuda_runtime.h>
#include <cuda_fp16.h>
#include <math.h>
#include <stdint.h>

#define BS 128
#define SL 512
#define HD 1024
#define DD 512
#define M_TOTAL (BS * SL)          // 65536
#define KPHYS 2048                 // [hi | lo] physical K (halves)
#define KVIRT 3072                 // 3 split terms
#define NEG_FILL -1000000.0f

#define BM 128
#define BN 128
#define BK 64
#define NCHUNK (KVIRT / BK)        // 48
#define STAGES 4
#define A_BYTES (BM * BK * 2)
#define B_BYTES (BN * BK * 2)
#define STAGE_BYTES (A_BYTES + B_BYTES)
#define SMEM_RED (128 * 2 * 4)
#define SMEM_GEMM (STAGES * STAGE_BYTES + SMEM_RED)
#define MAX_TILES (M_TOTAL / BM)   // 512

// ---------------- device scratch (no allocations allowed) -------------------
__device__ __half g_A[(size_t)M_TOTAL * KPHYS];   // 268 MB (upper bound)
__device__ __half g_B[(size_t)DD * KPHYS];        // 2 MB
__device__ float  g_spart[M_TOTAL * 4];
__device__ float  g_w[M_TOTAL];
__device__ int    g_cnt[BS];
__device__ int    g_off[BS];
__device__ int    g_total;
__device__ int    g_dst[M_TOTAL];                 // m -> compacted row or -1
__device__ int    g_src[M_TOTAL];                 // compacted row -> m

// ---------------- helpers ----------------------------------------------------
__device__ __forceinline__ uint32_t smem_u32(const void* p) {
    uint32_t a;
    asm("{ .reg .u64 t; cvta.to.shared.u64 t, %1; cvt.u32.u64 %0, t; }" : "=r"(a) : "l"(p));
    return a;
}
#define CP16(dst, src) \
    asm volatile("cp.async.cg.shared.global [%0], [%1], 16;" :: "r"(dst), "l"(src) : "memory")
#define CP_COMMIT() asm volatile("cp.async.commit_group;" ::: "memory")
#define CP_WAIT2()  asm volatile("cp.async.wait_group 2;" ::: "memory")

__device__ __forceinline__ void ldsm_x4(uint32_t addr, uint32_t& r0, uint32_t& r1,
                                        uint32_t& r2, uint32_t& r3) {
    asm volatile("ldmatrix.sync.aligned.m8n8.x4.shared.b16 {%0,%1,%2,%3}, [%4];"
                 : "=r"(r0), "=r"(r1), "=r"(r2), "=r"(r3) : "r"(addr));
}
__device__ __forceinline__ void mma16816(float* c, const uint32_t* a,
                                         uint32_t b0, uint32_t b1) {
    asm volatile(
        "mma.sync.aligned.m16n8k16.row.col.f32.f16.f16.f32 "
        "{%0,%1,%2,%3},{%4,%5,%6,%7},{%8,%9},{%0,%1,%2,%3};"
        : "+f"(c[0]), "+f"(c[1]), "+f"(c[2]), "+f"(c[3])
        : "r"(a[0]), "r"(a[1]), "r"(a[2]), "r"(a[3]), "r"(b0), "r"(b1));
}

// ---------------------------------------------------------------------------
// Compaction pipeline
// ---------------------------------------------------------------------------
__global__ __launch_bounds__(512) void count_kernel(const int* __restrict__ mask)
{
    const int b = blockIdx.x;
    const int keep = (mask[b * SL + threadIdx.x] == 0);
    const int cnt = __syncthreads_count(keep);
    if (threadIdx.x == 0) g_cnt[b] = cnt;
}

__global__ __launch_bounds__(128) void offset_kernel()
{
    __shared__ int c[BS];
    const int t = threadIdx.x;
    c[t] = g_cnt[t];
    __syncthreads();
#pragma unroll
    for (int d = 1; d < BS; d <<= 1) {
        int v = (t >= d) ? c[t - d] : 0;
        __syncthreads();
        c[t] += v;
        __syncthreads();
    }
    g_off[t] = c[t] - g_cnt[t];          // exclusive
    if (t == BS - 1) g_total = c[t];
}

__global__ __launch_bounds__(512) void map_kernel(const int* __restrict__ mask)
{
    __shared__ int pre[SL];
    const int b = blockIdx.x, s = threadIdx.x;
    const int m = b * SL + s;
    const int v = (mask[m] == 0);
    pre[s] = v;
    __syncthreads();
#pragma unroll
    for (int d = 1; d < SL; d <<= 1) {
        int t = (s >= d) ? pre[s - d] : 0;
        __syncthreads();
        pre[s] += t;
        __syncthreads();
    }
    const int r = g_off[b] + pre[s] - v;  // exclusive prefix
    g_dst[m] = v ? r : -1;
    if (v) g_src[r] = m;
}

// ---------------------------------------------------------------------------
// Gather + fp32 -> [hi | lo] fp16 split for unmasked rows only.
// grid = 256 blocks x 256 threads; each block strides over compacted rows.
// ---------------------------------------------------------------------------
__global__ __launch_bounds__(256) void conv_x_kernel(const float* __restrict__ x)
{
    const int total = g_total;
    const int t = threadIdx.x;
    for (int r = blockIdx.x; r < total; r += 256) {
        const float* src = x + (size_t)g_src[r] * HD + (t << 2);
        const float4 v = *reinterpret_cast<const float4*>(src);

        __half h0 = __float2half_rn(v.x), h1 = __float2half_rn(v.y);
        __half h2 = __float2half_rn(v.z), h3 = __float2half_rn(v.w);
        __half l0 = __float2half_rn(v.x - __half2float(h0));
        __half l1 = __float2half_rn(v.y - __half2float(h1));
        __half l2 = __float2half_rn(v.z - __half2float(h2));
        __half l3 = __float2half_rn(v.w - __half2float(h3));

        __half2* ph = reinterpret_cast<__half2*>(g_A + (size_t)r * KPHYS + (t << 2));
        __half2* pl = reinterpret_cast<__half2*>(g_A + (size_t)r * KPHYS + 1024 + (t << 2));
        ph[0] = __halves2half2(h0, h1); ph[1] = __halves2half2(h2, h3);
        pl[0] = __halves2half2(l0, l1); pl[1] = __halves2half2(l2, l3);
    }
}

__global__ __launch_bounds__(256) void conv_w_kernel(const float* __restrict__ Wq)
{
    size_t g = (size_t)blockIdx.x * 256 + threadIdx.x;
    size_t n = g >> 8;
    int kq = (int)(g & 255) << 2;
    float4 v = *reinterpret_cast<const float4*>(Wq + n * HD + kq);

    __half h0 = __float2half_rn(v.x), h1 = __float2half_rn(v.y);
    __half h2 = __float2half_rn(v.z), h3 = __float2half_rn(v.w);
    __half l0 = __float2half_rn(v.x - __half2float(h0));
    __half l1 = __float2half_rn(v.y - __half2float(h1));
    __half l2 = __float2half_rn(v.z - __half2float(h2));
    __half l3 = __float2half_rn(v.w - __half2float(h3));

    __half2* ph = reinterpret_cast<__half2*>(g_B + n * KPHYS + kq);
    __half2* pl = reinterpret_cast<__half2*>(g_B + n * KPHYS + 1024 + kq);
    ph[0] = __halves2half2(h0, h1); ph[1] = __halves2half2(h2, h3);
    pl[0] = __halves2half2(l0, l1); pl[1] = __halves2half2(l2, l3);
}

// ---------------------------------------------------------------------------
// GEMM over compacted rows; grid = (4 n-blocks, MAX_TILES m-tiles), early exit.
// ---------------------------------------------------------------------------
__device__ __forceinline__ void load_chunk(int chunk, uint32_t stage, int m0, int n0,
                                           int tid)
{
    const int kv = chunk * BK;
    const int kA = (kv < 2048) ? kv : kv - 2048;   // [hi | lo | hi]
    const int kB = (kv < 1024) ? kv : kv - 1024;   // [hi | hi | lo]
    const __half* asrc = g_A + (size_t)m0 * KPHYS + kA;
    const __half* bsrc = g_B + (size_t)n0 * KPHYS + kB;

#pragma unroll
    for (int u = 0; u < 4; u++) {
        int idx = tid + u * 256;
        int r = idx >> 3, j = idx & 7;
        uint32_t dst = stage + r * 128 + ((j ^ (r & 7)) << 4);
        CP16(dst, asrc + (size_t)r * KPHYS + j * 8);
    }
#pragma unroll
    for (int u = 0; u < 4; u++) {
        int idx = tid + u * 256;
        int r = idx >> 3, j = idx & 7;
        uint32_t dst = stage + A_BYTES + r * 128 + ((j ^ (r & 7)) << 4);
        CP16(dst, bsrc + (size_t)r * KPHYS + j * 8);
    }
    CP_COMMIT();
}

__global__ __launch_bounds__(256, 1) void gemm_kernel(const float* __restrict__ bq,
                                                      const float* __restrict__ vq)
{
    const int ntiles = (g_total + BM - 1) >> 7;
    if ((int)blockIdx.y >= ntiles) return;

    extern __shared__ char smem[];
    const uint32_t sb = smem_u32(smem);
    const int tid = threadIdx.x;
    const int wid = tid >> 5, lane = tid & 31;
    const int wm = wid & 3, wn = wid >> 2;
    const int m0 = blockIdx.y * BM;
    const int nb = blockIdx.x;
    const int n0 = nb * BN;

    float acc[2][8][4];
#pragma unroll
    for (int i = 0; i < 2; i++)
#pragma unroll
        for (int j = 0; j < 8; j++)
#pragma unroll
            for (int k = 0; k < 4; k++) acc[i][j][k] = 0.0f;

    const int arow = wm * 32 + (lane & 15);
    const int aj   = (lane >> 4);
    const int brow = wn * 64 + (lane & 7) + ((lane >> 4) & 1) * 8;
    const int bj   = ((lane >> 3) & 1);

    load_chunk(0, sb + 0 * STAGE_BYTES, m0, n0, tid);
    load_chunk(1, sb + 1 * STAGE_BYTES, m0, n0, tid);
    load_chunk(2, sb + 2 * STAGE_BYTES, m0, n0, tid);

#pragma unroll 1
    for (int i = 0; i < NCHUNK; i++) {
        CP_WAIT2();
        __syncthreads();

        const uint32_t sA = sb + (i & 3) * STAGE_BYTES;
        const uint32_t sB = sA + A_BYTES;

#pragma unroll
        for (int kk = 0; kk < 4; kk++) {
            uint32_t a0[4], a1[4];
            {
                int r = arow, j = kk * 2 + aj;
                ldsm_x4(sA + r * 128 + ((j ^ (r & 7)) << 4), a0[0], a0[1], a0[2], a0[3]);
                r = arow + 16;
                ldsm_x4(sA + r * 128 + ((j ^ (r & 7)) << 4), a1[0], a1[1], a1[2], a1[3]);
            }
#pragma unroll
            for (int nt2 = 0; nt2 < 4; nt2++) {
                uint32_t b0, b1, b2, b3;
                int r = brow + nt2 * 16, j = kk * 2 + bj;
                ldsm_x4(sB + r * 128 + ((j ^ (r & 7)) << 4), b0, b1, b2, b3);
                mma16816(acc[0][2 * nt2],     a0, b0, b1);
                mma16816(acc[0][2 * nt2 + 1], a0, b2, b3);
                mma16816(acc[1][2 * nt2],     a1, b0, b1);
                mma16816(acc[1][2 * nt2 + 1], a1, b2, b3);
            }
        }

        __syncthreads();
        if (i + 3 < NCHUNK)
            load_chunk(i + 3, sb + ((i + 3) & 3) * STAGE_BYTES, m0, n0, tid);
    }

    // ---- epilogue: per-row sum of vq[n]*tanh(D+bq[n]) over this 128-n block ----
    float* sred = reinterpret_cast<float*>(smem + STAGES * STAGE_BYTES);
    const int g = lane >> 2, tig = lane & 3;

    float rs[2][2] = {{0.f, 0.f}, {0.f, 0.f}};
#pragma unroll
    for (int mt = 0; mt < 2; mt++) {
#pragma unroll
        for (int nt = 0; nt < 8; nt++) {
            const int n = n0 + wn * 64 + nt * 8 + 2 * tig;
            const float b0 = __ldg(bq + n), b1 = __ldg(bq + n + 1);
            const float v0 = __ldg(vq + n), v1 = __ldg(vq + n + 1);
            rs[mt][0] += v0 * tanhf(acc[mt][nt][0] + b0) + v1 * tanhf(acc[mt][nt][1] + b1);
            rs[mt][1] += v0 * tanhf(acc[mt][nt][2] + b0) + v1 * tanhf(acc[mt][nt][3] + b1);
        }
    }
#pragma unroll
    for (int d = 1; d <= 2; d <<= 1) {
#pragma unroll
        for (int mt = 0; mt < 2; mt++) {
            rs[mt][0] += __shfl_xor_sync(0xFFFFFFFF, rs[mt][0], d);
            rs[mt][1] += __shfl_xor_sync(0xFFFFFFFF, rs[mt][1], d);
        }
    }
    if (tig == 0) {
#pragma unroll
        for (int mt = 0; mt < 2; mt++) {
            sred[(wm * 32 + mt * 16 + g) * 2 + wn]     = rs[mt][0];
            sred[(wm * 32 + mt * 16 + g + 8) * 2 + wn] = rs[mt][1];
        }
    }
    __syncthreads();
    if (tid < 128)
        g_spart[(size_t)(m0 + tid) * 4 + nb] = sred[tid * 2] + sred[tid * 2 + 1];
}

// ---------------------------------------------------------------------------
// Softmax per batch over scattered scores (masked -> NEG_FILL).
// ---------------------------------------------------------------------------
__global__ __launch_bounds__(256) void softmax_kernel()
{
    __shared__ float sc[SL];
    __shared__ float red[256];
    const int b = blockIdx.x, t = threadIdx.x;

    for (int s = t; s < SL; s += 256) {
        const int m = b * SL + s;
        const int d = g_dst[m];
        float v = NEG_FILL;
        if (d >= 0)
            v = g_spart[(size_t)d * 4 + 0] + g_spart[(size_t)d * 4 + 1]
              + g_spart[(size_t)d * 4 + 2] + g_spart[(size_t)d * 4 + 3];
        sc[s] = v;
    }
    __syncthreads();

    red[t] = fmaxf(sc[t], sc[t + 256]);
    __syncthreads();
    for (int off = 128; off > 0; off >>= 1) {
        if (t < off) red[t] = fmaxf(red[t], red[t + off]);
        __syncthreads();
    }
    const float gm = red[0];
    __syncthreads();

    const float e0 = __expf(sc[t] - gm);
    const float e1 = __expf(sc[t + 256] - gm);
    red[t] = e0 + e1;
    __syncthreads();
    for (int off = 128; off > 0; off >>= 1) {
        if (t < off) red[t] += red[t + off];
        __syncthreads();
    }
    const float inv = 1.0f / red[0];
    g_w[b * SL + t] = e0 * inv;
    g_w[b * SL + t + 256] = e1 * inv;
}

// ---------------------------------------------------------------------------
// Weighted sum skipping zero-weight (masked) rows.  grid (4, 128).
// ---------------------------------------------------------------------------
__global__ __launch_bounds__(256) void wsum_kernel(const float* __restrict__ x,
                                                   float* __restrict__ out)
{
    __shared__ float w[SL];
    const int b = blockIdx.y;
    const int col = blockIdx.x * 256 + threadIdx.x;

    w[threadIdx.x] = g_w[b * SL + threadIdx.x];
    w[threadIdx.x + 256] = g_w[b * SL + threadIdx.x + 256];
    __syncthreads();

    const float* xp = x + (size_t)b * SL * HD + col;
    float acc = 0.0f;
#pragma unroll 1
    for (int s = 0; s < SL; s += 4) {
        const float w0 = w[s], w1 = w[s + 1], w2 = w[s + 2], w3 = w[s + 3];
        if (w0 != 0.0f) acc += w0 * __ldg(xp + (size_t)s * HD);
        if (w1 != 0.0f) acc += w1 * __ldg(xp + (size_t)(s + 1) * HD);
        if (w2 != 0.0f) acc += w2 * __ldg(xp + (size_t)(s + 2) * HD);
        if (w3 != 0.0f) acc += w3 * __ldg(xp + (size_t)(s + 3) * HD);
    }
    out[(size_t)b * HD + col] = acc;
}

// ---------------------------------------------------------------------------
extern "C" void kernel_launch(void* const* d_in, const int* in_sizes, int n_in,
                              void* d_out, int out_size)
{
    const float* x    = (const float*)d_in[0];   // [128,512,1024] f32
    const int*   mask = (const int*)  d_in[1];   // [128,512] int32
    const float* Wq   = (const float*)d_in[2];   // [512,1024] f32
    const float* bq   = (const float*)d_in[3];   // [512] f32
    const float* vq   = (const float*)d_in[4];   // [512] f32
    float* out = (float*)d_out;                  // [128,1024] f32

    cudaFuncSetAttribute(gemm_kernel, cudaFuncAttributeMaxDynamicSharedMemorySize, SMEM_GEMM);

    count_kernel<<<BS, SL>>>(mask);
    offset_kernel<<<1, BS>>>();
    map_kernel<<<BS, SL>>>(mask);
    conv_x_kernel<<<256, 256>>>(x);
    conv_w_kernel<<<(DD * HD / 4) / 256, 256>>>(Wq);
    gemm_kernel<<<dim3(DD / BN, MAX_TILES), 256, SMEM_GEMM>>>(bq, vq);
    softmax_kernel<<<BS, 256>>>();
    wsum_kernel<<<dim3(4, BS), 256>>>(x, out);
}

// round 5
// speedup vs baseline: 5.7926x; 1.3298x over previous
#include <cuda_runtime.h>
#include <cuda_fp16.h>
#include <math.h>
#include <stdint.h>

#define BS 128
#define SL 512
#define HD 1024
#define DD 512
#define M_TOTAL (BS * SL)          // 65536
#define KPHYS 2048                 // [hi | lo] physical K (halves)
#define NEG_FILL -1000000.0f

#define BM 128
#define BN 128
#define BK 64
#define NCHUNK_P 16                // physical K chunks (1024 / 64)
#define STAGES 3
#define T_BYTES (128 * BK * 2)     // one 128-row x 64-half tile = 16384
#define A_HI 0
#define A_LO T_BYTES
#define B_HI (2 * T_BYTES)
#define B_LO (3 * T_BYTES)
#define STAGE_BYTES (4 * T_BYTES)  // 65536
#define SMEM_RED (128 * 2 * 4)
#define SMEM_GEMM (STAGES * STAGE_BYTES + SMEM_RED)   // 197632
#define MAX_TILES (M_TOTAL / BM)   // 512

// ---------------- device scratch (no allocations allowed) -------------------
__device__ __half g_A[(size_t)M_TOTAL * KPHYS];   // 268 MB (upper bound)
__device__ __half g_B[(size_t)DD * KPHYS];        // 2 MB
__device__ float  g_spart[M_TOTAL * 4];
__device__ float  g_w[M_TOTAL];
__device__ int    g_cnt[BS];
__device__ int    g_off[BS];
__device__ int    g_total;
__device__ int    g_dst[M_TOTAL];                 // m -> compacted row or -1
__device__ int    g_src[M_TOTAL];                 // compacted row -> m

// ---------------- helpers ----------------------------------------------------
__device__ __forceinline__ uint32_t smem_u32(const void* p) {
    uint32_t a;
    asm("{ .reg .u64 t; cvta.to.shared.u64 t, %1; cvt.u32.u64 %0, t; }" : "=r"(a) : "l"(p));
    return a;
}
#define CP16(dst, src) \
    asm volatile("cp.async.cg.shared.global [%0], [%1], 16;" :: "r"(dst), "l"(src) : "memory")
#define CP_COMMIT() asm volatile("cp.async.commit_group;" ::: "memory")
#define CP_WAIT1()  asm volatile("cp.async.wait_group 1;" ::: "memory")

__device__ __forceinline__ void ldsm_x4(uint32_t addr, uint32_t& r0, uint32_t& r1,
                                        uint32_t& r2, uint32_t& r3) {
    asm volatile("ldmatrix.sync.aligned.m8n8.x4.shared.b16 {%0,%1,%2,%3}, [%4];"
                 : "=r"(r0), "=r"(r1), "=r"(r2), "=r"(r3) : "r"(addr));
}
__device__ __forceinline__ void mma16816(float* c, const uint32_t* a,
                                         uint32_t b0, uint32_t b1) {
    asm volatile(
        "mma.sync.aligned.m16n8k16.row.col.f32.f16.f16.f32 "
        "{%0,%1,%2,%3},{%4,%5,%6,%7},{%8,%9},{%0,%1,%2,%3};"
        : "+f"(c[0]), "+f"(c[1]), "+f"(c[2]), "+f"(c[3])
        : "r"(a[0]), "r"(a[1]), "r"(a[2]), "r"(a[3]), "r"(b0), "r"(b1));
}

// ---------------------------------------------------------------------------
// Compaction pipeline
// ---------------------------------------------------------------------------
__global__ __launch_bounds__(512) void count_kernel(const int* __restrict__ mask)
{
    const int b = blockIdx.x;
    const int keep = (mask[b * SL + threadIdx.x] == 0);
    const int cnt = __syncthreads_count(keep);
    if (threadIdx.x == 0) g_cnt[b] = cnt;
}

__global__ __launch_bounds__(128) void offset_kernel()
{
    __shared__ int c[BS];
    const int t = threadIdx.x;
    c[t] = g_cnt[t];
    __syncthreads();
#pragma unroll
    for (int d = 1; d < BS; d <<= 1) {
        int v = (t >= d) ? c[t - d] : 0;
        __syncthreads();
        c[t] += v;
        __syncthreads();
    }
    g_off[t] = c[t] - g_cnt[t];          // exclusive
    if (t == BS - 1) g_total = c[t];
}

__global__ __launch_bounds__(512) void map_kernel(const int* __restrict__ mask)
{
    __shared__ int pre[SL];
    const int b = blockIdx.x, s = threadIdx.x;
    const int m = b * SL + s;
    const int v = (mask[m] == 0);
    pre[s] = v;
    __syncthreads();
#pragma unroll
    for (int d = 1; d < SL; d <<= 1) {
        int t = (s >= d) ? pre[s - d] : 0;
        __syncthreads();
        pre[s] += t;
        __syncthreads();
    }
    const int r = g_off[b] + pre[s] - v;  // exclusive prefix
    g_dst[m] = v ? r : -1;
    if (v) g_src[r] = m;
}

// ---------------------------------------------------------------------------
// Gather + fp32 -> [hi | lo] fp16 split for unmasked rows only.
// grid = 16384 blocks; each block handles ~2 compacted rows (high MLP).
// ---------------------------------------------------------------------------
__global__ __launch_bounds__(256) void conv_x_kernel(const float* __restrict__ x)
{
    const int total = g_total;
    const int t = threadIdx.x;
    for (int r = blockIdx.x; r < total; r += 16384) {
        const float* src = x + (size_t)g_src[r] * HD + (t << 2);
        const float4 v = *reinterpret_cast<const float4*>(src);

        __half h0 = __float2half_rn(v.x), h1 = __float2half_rn(v.y);
        __half h2 = __float2half_rn(v.z), h3 = __float2half_rn(v.w);
        __half l0 = __float2half_rn(v.x - __half2float(h0));
        __half l1 = __float2half_rn(v.y - __half2float(h1));
        __half l2 = __float2half_rn(v.z - __half2float(h2));
        __half l3 = __float2half_rn(v.w - __half2float(h3));

        __half2* ph = reinterpret_cast<__half2*>(g_A + (size_t)r * KPHYS + (t << 2));
        __half2* pl = reinterpret_cast<__half2*>(g_A + (size_t)r * KPHYS + 1024 + (t << 2));
        ph[0] = __halves2half2(h0, h1); ph[1] = __halves2half2(h2, h3);
        pl[0] = __halves2half2(l0, l1); pl[1] = __halves2half2(l2, l3);
    }
}

__global__ __launch_bounds__(256) void conv_w_kernel(const float* __restrict__ Wq)
{
    size_t g = (size_t)blockIdx.x * 256 + threadIdx.x;
    size_t n = g >> 8;
    int kq = (int)(g & 255) << 2;
    float4 v = *reinterpret_cast<const float4*>(Wq + n * HD + kq);

    __half h0 = __float2half_rn(v.x), h1 = __float2half_rn(v.y);
    __half h2 = __float2half_rn(v.z), h3 = __float2half_rn(v.w);
    __half l0 = __float2half_rn(v.x - __half2float(h0));
    __half l1 = __float2half_rn(v.y - __half2float(h1));
    __half l2 = __float2half_rn(v.z - __half2float(h2));
    __half l3 = __float2half_rn(v.w - __half2float(h3));

    __half2* ph = reinterpret_cast<__half2*>(g_B + n * KPHYS + kq);
    __half2* pl = reinterpret_cast<__half2*>(g_B + n * KPHYS + 1024 + kq);
    ph[0] = __halves2half2(h0, h1); ph[1] = __halves2half2(h2, h3);
    pl[0] = __halves2half2(l0, l1); pl[1] = __halves2half2(l2, l3);
}

// ---------------------------------------------------------------------------
// GEMM over compacted rows; 16 physical K-chunks, each stage holds
// {A_hi, A_lo, B_hi, B_lo}; 3 split-term MMA passes share smem loads.
// grid = (4 n-blocks, MAX_TILES m-tiles), early exit on compacted count.
// ---------------------------------------------------------------------------
__device__ __forceinline__ void load_chunk(int chunk, uint32_t stage, int m0, int n0,
                                           int tid)
{
    const int k = chunk * BK;
    const __half* ah = g_A + (size_t)m0 * KPHYS + k;
    const __half* bh = g_B + (size_t)n0 * KPHYS + k;

#pragma unroll
    for (int u = 0; u < 4; u++) {
        int idx = tid + u * 256;
        int r = idx >> 3, j = idx & 7;
        uint32_t sw = r * 128 + ((j ^ (r & 7)) << 4);
        const size_t go = (size_t)r * KPHYS + j * 8;
        CP16(stage + A_HI + sw, ah + go);
        CP16(stage + A_LO + sw, ah + 1024 + go);
        CP16(stage + B_HI + sw, bh + go);
        CP16(stage + B_LO + sw, bh + 1024 + go);
    }
    CP_COMMIT();
}

__global__ __launch_bounds__(256, 1) void gemm_kernel(const float* __restrict__ bq,
                                                      const float* __restrict__ vq)
{
    const int ntiles = (g_total + BM - 1) >> 7;
    if ((int)blockIdx.y >= ntiles) return;

    extern __shared__ char smem[];
    const uint32_t sb = smem_u32(smem);
    const int tid = threadIdx.x;
    const int wid = tid >> 5, lane = tid & 31;
    const int wm = wid & 3, wn = wid >> 2;
    const int m0 = blockIdx.y * BM;
    const int nb = blockIdx.x;
    const int n0 = nb * BN;

    float acc[2][8][4];
#pragma unroll
    for (int i = 0; i < 2; i++)
#pragma unroll
        for (int j = 0; j < 8; j++)
#pragma unroll
            for (int k = 0; k < 4; k++) acc[i][j][k] = 0.0f;

    const int arow = wm * 32 + (lane & 15);
    const int aj   = (lane >> 4);
    const int brow = wn * 64 + (lane & 7) + ((lane >> 4) & 1) * 8;
    const int bj   = ((lane >> 3) & 1);

    load_chunk(0, sb + 0 * STAGE_BYTES, m0, n0, tid);
    load_chunk(1, sb + 1 * STAGE_BYTES, m0, n0, tid);

#pragma unroll 1
    for (int i = 0; i < NCHUNK_P; i++) {
        CP_WAIT1();                 // chunk i resident
        __syncthreads();

        const uint32_t st = sb + (i % 3) * STAGE_BYTES;

#pragma unroll
        for (int kk = 0; kk < 4; kk++) {
            uint32_t ah0[4], ah1[4], al0[4], al1[4];
            const int j = kk * 2 + aj;
            {
                int r = arow;
                uint32_t sw = r * 128 + ((j ^ (r & 7)) << 4);
                ldsm_x4(st + A_HI + sw, ah0[0], ah0[1], ah0[2], ah0[3]);
                ldsm_x4(st + A_LO + sw, al0[0], al0[1], al0[2], al0[3]);
                r = arow + 16;
                sw = r * 128 + ((j ^ (r & 7)) << 4);
                ldsm_x4(st + A_HI + sw, ah1[0], ah1[1], ah1[2], ah1[3]);
                ldsm_x4(st + A_LO + sw, al1[0], al1[1], al1[2], al1[3]);
            }
#pragma unroll
            for (int nt2 = 0; nt2 < 4; nt2++) {
                const int r = brow + nt2 * 16;
                const int jb = kk * 2 + bj;
                const uint32_t sw = r * 128 + ((jb ^ (r & 7)) << 4);
                uint32_t h0, h1, h2, h3, l0, l1, l2, l3;
                ldsm_x4(st + B_HI + sw, h0, h1, h2, h3);
                ldsm_x4(st + B_LO + sw, l0, l1, l2, l3);
                // A_hi * B_hi
                mma16816(acc[0][2 * nt2],     ah0, h0, h1);
                mma16816(acc[0][2 * nt2 + 1], ah0, h2, h3);
                mma16816(acc[1][2 * nt2],     ah1, h0, h1);
                mma16816(acc[1][2 * nt2 + 1], ah1, h2, h3);
                // A_lo * B_hi
                mma16816(acc[0][2 * nt2],     al0, h0, h1);
                mma16816(acc[0][2 * nt2 + 1], al0, h2, h3);
                mma16816(acc[1][2 * nt2],     al1, h0, h1);
                mma16816(acc[1][2 * nt2 + 1], al1, h2, h3);
                // A_hi * B_lo
                mma16816(acc[0][2 * nt2],     ah0, l0, l1);
                mma16816(acc[0][2 * nt2 + 1], ah0, l2, l3);
                mma16816(acc[1][2 * nt2],     ah1, l0, l1);
                mma16816(acc[1][2 * nt2 + 1], ah1, l2, l3);
            }
        }

        __syncthreads();
        if (i + 2 < NCHUNK_P)
            load_chunk(i + 2, sb + ((i + 2) % 3) * STAGE_BYTES, m0, n0, tid);
    }

    // ---- epilogue: per-row sum of vq[n]*tanh(D+bq[n]) over this 128-n block ----
    float* sred = reinterpret_cast<float*>(smem + STAGES * STAGE_BYTES);
    const int g = lane >> 2, tig = lane & 3;

    float rs[2][2] = {{0.f, 0.f}, {0.f, 0.f}};
#pragma unroll
    for (int mt = 0; mt < 2; mt++) {
#pragma unroll
        for (int nt = 0; nt < 8; nt++) {
            const int n = n0 + wn * 64 + nt * 8 + 2 * tig;
            const float b0 = __ldg(bq + n), b1 = __ldg(bq + n + 1);
            const float v0 = __ldg(vq + n), v1 = __ldg(vq + n + 1);
            rs[mt][0] += v0 * tanhf(acc[mt][nt][0] + b0) + v1 * tanhf(acc[mt][nt][1] + b1);
            rs[mt][1] += v0 * tanhf(acc[mt][nt][2] + b0) + v1 * tanhf(acc[mt][nt][3] + b1);
        }
    }
#pragma unroll
    for (int d = 1; d <= 2; d <<= 1) {
#pragma unroll
        for (int mt = 0; mt < 2; mt++) {
            rs[mt][0] += __shfl_xor_sync(0xFFFFFFFF, rs[mt][0], d);
            rs[mt][1] += __shfl_xor_sync(0xFFFFFFFF, rs[mt][1], d);
        }
    }
    if (tig == 0) {
#pragma unroll
        for (int mt = 0; mt < 2; mt++) {
            sred[(wm * 32 + mt * 16 + g) * 2 + wn]     = rs[mt][0];
            sred[(wm * 32 + mt * 16 + g + 8) * 2 + wn] = rs[mt][1];
        }
    }
    __syncthreads();
    if (tid < 128)
        g_spart[(size_t)(m0 + tid) * 4 + nb] = sred[tid * 2] + sred[tid * 2 + 1];
}

// ---------------------------------------------------------------------------
// Softmax per batch over scattered scores (masked -> NEG_FILL).
// ---------------------------------------------------------------------------
__global__ __launch_bounds__(256) void softmax_kernel()
{
    __shared__ float sc[SL];
    __shared__ float red[256];
    const int b = blockIdx.x, t = threadIdx.x;

    for (int s = t; s < SL; s += 256) {
        const int m = b * SL + s;
        const int d = g_dst[m];
        float v = NEG_FILL;
        if (d >= 0)
            v = g_spart[(size_t)d * 4 + 0] + g_spart[(size_t)d * 4 + 1]
              + g_spart[(size_t)d * 4 + 2] + g_spart[(size_t)d * 4 + 3];
        sc[s] = v;
    }
    __syncthreads();

    red[t] = fmaxf(sc[t], sc[t + 256]);
    __syncthreads();
    for (int off = 128; off > 0; off >>= 1) {
        if (t < off) red[t] = fmaxf(red[t], red[t + off]);
        __syncthreads();
    }
    const float gm = red[0];
    __syncthreads();

    const float e0 = __expf(sc[t] - gm);
    const float e1 = __expf(sc[t + 256] - gm);
    red[t] = e0 + e1;
    __syncthreads();
    for (int off = 128; off > 0; off >>= 1) {
        if (t < off) red[t] += red[t + off];
        __syncthreads();
    }
    const float inv = 1.0f / red[0];
    g_w[b * SL + t] = e0 * inv;
    g_w[b * SL + t + 256] = e1 * inv;
}

// ---------------------------------------------------------------------------
// Weighted sum skipping zero-weight (masked) rows.  grid (4, 128).
// ---------------------------------------------------------------------------
__global__ __launch_bounds__(256) void wsum_kernel(const float* __restrict__ x,
                                                   float* __restrict__ out)
{
    __shared__ float w[SL];
    const int b = blockIdx.y;
    const int col = blockIdx.x * 256 + threadIdx.x;

    w[threadIdx.x] = g_w[b * SL + threadIdx.x];
    w[threadIdx.x + 256] = g_w[b * SL + threadIdx.x + 256];
    __syncthreads();

    const float* xp = x + (size_t)b * SL * HD + col;
    float acc = 0.0f;
#pragma unroll 1
    for (int s = 0; s < SL; s += 4) {
        const float w0 = w[s], w1 = w[s + 1], w2 = w[s + 2], w3 = w[s + 3];
        if (w0 != 0.0f) acc += w0 * __ldg(xp + (size_t)s * HD);
        if (w1 != 0.0f) acc += w1 * __ldg(xp + (size_t)(s + 1) * HD);
        if (w2 != 0.0f) acc += w2 * __ldg(xp + (size_t)(s + 2) * HD);
        if (w3 != 0.0f) acc += w3 * __ldg(xp + (size_t)(s + 3) * HD);
    }
    out[(size_t)b * HD + col] = acc;
}

// ---------------------------------------------------------------------------
extern "C" void kernel_launch(void* const* d_in, const int* in_sizes, int n_in,
                              void* d_out, int out_size)
{
    const float* x    = (const float*)d_in[0];   // [128,512,1024] f32
    const int*   mask = (const int*)  d_in[1];   // [128,512] int32
    const float* Wq   = (const float*)d_in[2];   // [512,1024] f32
    const float* bq   = (const float*)d_in[3];   // [512] f32
    const float* vq   = (const float*)d_in[4];   // [512] f32
    float* out = (float*)d_out;                  // [128,1024] f32

    cudaFuncSetAttribute(gemm_kernel, cudaFuncAttributeMaxDynamicSharedMemorySize, SMEM_GEMM);

    count_kernel<<<BS, SL>>>(mask);
    offset_kernel<<<1, BS>>>();
    map_kernel<<<BS, SL>>>(mask);
    conv_x_kernel<<<16384, 256>>>(x);
    conv_w_kernel<<<(DD * HD / 4) / 256, 256>>>(Wq);
    gemm_kernel<<<dim3(DD / BN, MAX_TILES), 256, SMEM_GEMM>>>(bq, vq);
    softmax_kernel<<<BS, 256>>>();
    wsum_kernel<<<dim3(4, BS), 256>>>(x, out);
}